// round 15
// baseline (speedup 1.0000x reference)
#include <cuda_runtime.h>
#include <cuda_fp16.h>
#include <cstdint>

#define N_NODES 50000
#define N_EDGES 800000
#define D 128
#define D4 (D / 4)
#define FULL 0xffffffffu
#define SCAN_B 1024
#define N_BLKS ((N_NODES + SCAN_B - 1) / SCAN_B)   // 49

// Static device scratch (no allocation; zero-initialized at load).
__device__ int   g_deg[N_NODES];
__device__ int   g_off[N_NODES + 1];
__device__ int   g_rank[N_EDGES];                  // edge's arrival rank within its dst bucket
__device__ int   g_csr[N_EDGES];
__device__ int   g_blk[64];                        // per-block scan sums
__device__ uint4 g_feat_h[(N_NODES + 1) * 16];     // fp16 rows; row N_NODES = zeros (never written)
__device__ uint4 g_hh[N_NODES * 16];               // fp16 aggregate h rows (256B)
__device__ uint2 g_Wh[D * D / 4];                  // fp16 W, row-major [k][n]

// ---------------------------------------------------------------------------
// K1: histogram + rank capture ONLY (feature/W conversion moved into bucket).
// The atomicAdd return value is each edge's stable slot within its dst bucket.
// g_deg cleared by the PREVIOUS execution's gemm kernel (zero at load).
// ---------------------------------------------------------------------------
__global__ void __launch_bounds__(256) hist_kernel(const int* __restrict__ edge_dst) {
    int i = blockIdx.x * blockDim.x + threadIdx.x;
    if (i < N_EDGES / 4) {
        int4 d = __ldg(reinterpret_cast<const int4*>(edge_dst) + i);
        int4 r;
        r.x = atomicAdd(&g_deg[d.x], 1);
        r.y = atomicAdd(&g_deg[d.y], 1);
        r.z = atomicAdd(&g_deg[d.z], 1);
        r.w = atomicAdd(&g_deg[d.w], 1);
        reinterpret_cast<int4*>(g_rank)[i] = r;      // coalesced
    }
}

// ---------------------------------------------------------------------------
// K2: per-block exclusive scan (coalesced). Block total -> g_blk.
// ---------------------------------------------------------------------------
__global__ void __launch_bounds__(SCAN_B) scan1_kernel() {
    __shared__ int s_wsum[32];
    int t = threadIdx.x, wid = t >> 5, lane = t & 31;
    int i = blockIdx.x * SCAN_B + t;
    int v = (i < N_NODES) ? g_deg[i] : 0;

    int x = v;
    #pragma unroll
    for (int d = 1; d < 32; d <<= 1) {
        int y = __shfl_up_sync(FULL, x, d);
        if (lane >= d) x += y;
    }
    if (lane == 31) s_wsum[wid] = x;
    __syncthreads();
    if (wid == 0) {
        int w = s_wsum[lane];
        int xx = w;
        #pragma unroll
        for (int d = 1; d < 32; d <<= 1) {
            int y = __shfl_up_sync(FULL, xx, d);
            if (lane >= d) xx += y;
        }
        s_wsum[lane] = xx - w;
        if (lane == 31) g_blk[blockIdx.x] = xx;
    }
    __syncthreads();

    if (i < N_NODES) g_off[i] = (x - v) + s_wsum[wid];
}

// ---------------------------------------------------------------------------
// K3: add block offsets; one warp re-scans the 49 totals.
// ---------------------------------------------------------------------------
__global__ void __launch_bounds__(SCAN_B) scan3_kernel() {
    __shared__ int s_off;
    int t = threadIdx.x;
    if (t < 32) {
        int v = 0;
        if (t < (int)blockIdx.x) v = g_blk[t];
        if (t + 32 < (int)blockIdx.x) v += g_blk[t + 32];
        #pragma unroll
        for (int d = 16; d >= 1; d >>= 1) v += __shfl_xor_sync(FULL, v, d);
        if (t == 0) s_off = v;
    }
    __syncthreads();

    int i = blockIdx.x * SCAN_B + t;
    if (i < N_NODES) g_off[i] = g_off[i] + s_off;
    if (i == 0) g_off[N_NODES] = N_EDGES;
}

// ---------------------------------------------------------------------------
// K4: bucket fill (atomic-free, 8 edges/thread) + feature/W f32->f16 convert
// as grid-stride side work. Bucket's edge path is latency-bound (issue 3.1%
// measured), so the independent cvt traffic rides in its stall slots.
// ---------------------------------------------------------------------------
__global__ void __launch_bounds__(256) bucket_kernel(const int* __restrict__ edge_src,
                                                     const int* __restrict__ edge_dst,
                                                     const float* __restrict__ feature,
                                                     const float* __restrict__ W) {
    int i = blockIdx.x * blockDim.x + threadIdx.x;
    int nthreads = gridDim.x * blockDim.x;   // 391 * 256 = 100096

    // ---- edge scatter: 8 edges, all offset loads independent ----
    if (i < N_EDGES / 8) {
        int4 d0 = __ldg(reinterpret_cast<const int4*>(edge_dst) + 2 * i);
        int4 d1 = __ldg(reinterpret_cast<const int4*>(edge_dst) + 2 * i + 1);
        int4 s0 = __ldg(reinterpret_cast<const int4*>(edge_src) + 2 * i);
        int4 s1 = __ldg(reinterpret_cast<const int4*>(edge_src) + 2 * i + 1);
        int4 r0 = reinterpret_cast<const int4*>(g_rank)[2 * i];
        int4 r1 = reinterpret_cast<const int4*>(g_rank)[2 * i + 1];
        int o0 = __ldg(&g_off[d0.x]);
        int o1 = __ldg(&g_off[d0.y]);
        int o2 = __ldg(&g_off[d0.z]);
        int o3 = __ldg(&g_off[d0.w]);
        int o4 = __ldg(&g_off[d1.x]);
        int o5 = __ldg(&g_off[d1.y]);
        int o6 = __ldg(&g_off[d1.z]);
        int o7 = __ldg(&g_off[d1.w]);
        g_csr[o0 + r0.x] = s0.x;
        g_csr[o1 + r0.y] = s0.y;
        g_csr[o2 + r0.z] = s0.z;
        g_csr[o3 + r0.w] = s0.w;
        g_csr[o4 + r1.x] = s1.x;
        g_csr[o5 + r1.y] = s1.y;
        g_csr[o6 + r1.z] = s1.z;
        g_csr[o7 + r1.w] = s1.w;
    }

    // ---- feature f32 -> f16 (1.6M float4 -> uint2), grid-stride ----
    for (int idx = i; idx < N_NODES * D4; idx += nthreads) {
        float4 v = __ldg(reinterpret_cast<const float4*>(feature) + idx);
        __half2 lo = __floats2half2_rn(v.x, v.y);
        __half2 hi = __floats2half2_rn(v.z, v.w);
        uint2 p;
        p.x = *reinterpret_cast<unsigned*>(&lo);
        p.y = *reinterpret_cast<unsigned*>(&hi);
        reinterpret_cast<uint2*>(g_feat_h)[idx] = p;
    }

    // ---- W f32 -> f16 (4096 float4) ----
    if (i < D * D / 4) {
        float4 v = __ldg(reinterpret_cast<const float4*>(W) + i);
        __half2 lo = __floats2half2_rn(v.x, v.y);
        __half2 hi = __floats2half2_rn(v.z, v.w);
        uint2 p;
        p.x = *reinterpret_cast<unsigned*>(&lo);
        p.y = *reinterpret_cast<unsigned*>(&hi);
        g_Wh[i] = p;
    }
}

// ---------------------------------------------------------------------------
// K5: aggregate — one warp per node, half-warp per fp16 row, uniform padded
// 8-edge body with TWO HADD2 tree levels before the fp32 accumulate
// (36 issues/body vs 48).
// ---------------------------------------------------------------------------
__device__ __forceinline__ void acc8(float* acc, uint4 a) {
    float2 f0 = __half22float2(*reinterpret_cast<__half2*>(&a.x));
    float2 f1 = __half22float2(*reinterpret_cast<__half2*>(&a.y));
    float2 f2 = __half22float2(*reinterpret_cast<__half2*>(&a.z));
    float2 f3 = __half22float2(*reinterpret_cast<__half2*>(&a.w));
    acc[0] += f0.x; acc[1] += f0.y; acc[2] += f1.x; acc[3] += f1.y;
    acc[4] += f2.x; acc[5] += f2.y; acc[6] += f3.x; acc[7] += f3.y;
}

__device__ __forceinline__ uint4 hadd2_u4(uint4 a, uint4 b) {
    uint4 r;
    __half2 x, y;
    x = *reinterpret_cast<__half2*>(&a.x); y = *reinterpret_cast<__half2*>(&b.x);
    x = __hadd2(x, y); r.x = *reinterpret_cast<unsigned*>(&x);
    x = *reinterpret_cast<__half2*>(&a.y); y = *reinterpret_cast<__half2*>(&b.y);
    x = __hadd2(x, y); r.y = *reinterpret_cast<unsigned*>(&x);
    x = *reinterpret_cast<__half2*>(&a.z); y = *reinterpret_cast<__half2*>(&b.z);
    x = __hadd2(x, y); r.z = *reinterpret_cast<unsigned*>(&x);
    x = *reinterpret_cast<__half2*>(&a.w); y = *reinterpret_cast<__half2*>(&b.w);
    x = __hadd2(x, y); r.w = *reinterpret_cast<unsigned*>(&x);
    return r;
}

__global__ void __launch_bounds__(256) agg_kernel() {
    int w = (blockIdx.x * blockDim.x + threadIdx.x) >> 5;
    int lane = threadIdx.x & 31;
    if (w >= N_NODES) return;
    int half = lane >> 4;
    int hl   = lane & 15;

    int j0 = g_off[w];
    int len = g_off[w + 1] - j0;

    const uint4* fh = g_feat_h;
    float acc[8];
    #pragma unroll
    for (int i = 0; i < 8; i++) acc[i] = 0.f;

    for (int base = 0; base < len; base += 32) {
        int rem = len - base;
        int nb = rem < 32 ? rem : 32;
        int myidx = N_NODES;                       // default: zero row
        if (base + lane < len) myidx = g_csr[j0 + base + lane];

        for (int t = 0; t < nb; t += 8) {          // always full 8-edge body
            int s0 = __shfl_sync(FULL, myidx, t + 0 + half);
            int s1 = __shfl_sync(FULL, myidx, t + 2 + half);
            int s2 = __shfl_sync(FULL, myidx, t + 4 + half);
            int s3 = __shfl_sync(FULL, myidx, t + 6 + half);
            uint4 a0 = __ldg(fh + (size_t)s0 * 16 + hl);
            uint4 a1 = __ldg(fh + (size_t)s1 * 16 + hl);
            uint4 a2 = __ldg(fh + (size_t)s2 * 16 + hl);
            uint4 a3 = __ldg(fh + (size_t)s3 * 16 + hl);
            uint4 p01 = hadd2_u4(a0, a1);
            uint4 p23 = hadd2_u4(a2, a3);
            uint4 q   = hadd2_u4(p01, p23);        // second tree level
            acc8(acc, q);
        }
    }

    #pragma unroll
    for (int i = 0; i < 8; i++)
        acc[i] += __shfl_xor_sync(FULL, acc[i], 16);

    if (half == 0) {
        __half2 h0 = __floats2half2_rn(acc[0], acc[1]);
        __half2 h1 = __floats2half2_rn(acc[2], acc[3]);
        __half2 h2 = __floats2half2_rn(acc[4], acc[5]);
        __half2 h3 = __floats2half2_rn(acc[6], acc[7]);
        uint4 p;
        p.x = *reinterpret_cast<unsigned*>(&h0);
        p.y = *reinterpret_cast<unsigned*>(&h1);
        p.z = *reinterpret_cast<unsigned*>(&h2);
        p.w = *reinterpret_cast<unsigned*>(&h3);
        g_hh[(size_t)w * 16 + hl] = p;
    }
}

// ---------------------------------------------------------------------------
// K6: out = relu(h @ W + b) via tensor cores (mma.m16n8k16 f16f16->f32).
// 64 rows per block; swizzled smem; clears g_deg for the NEXT execution.
// ---------------------------------------------------------------------------
__global__ void __launch_bounds__(256) gemm_kernel(const float* __restrict__ b,
                                                   float* __restrict__ out) {
    __shared__ uint4 sW[D * 16];    // 32 KB
    __shared__ uint4 sA[64 * 16];   // 16 KB

    int tid = threadIdx.x;
    int warp = tid >> 5;
    int lane = tid & 31;
    int warp_m = warp >> 1;
    int warp_n = warp & 1;
    int row0 = blockIdx.x * 64;

    {
        int gid = blockIdx.x * 256 + tid;
        if (gid < N_NODES) g_deg[gid] = 0;
    }

    #pragma unroll
    for (int it = 0; it < 8; it++) {
        int seg = tid + it * 256;
        int row = seg >> 4, u = seg & 15;
        sW[row * 16 + (u ^ (row & 7))] = reinterpret_cast<const uint4*>(g_Wh)[seg];
    }
    #pragma unroll
    for (int it = 0; it < 4; it++) {
        int seg = tid + it * 256;
        int r = seg >> 4, u = seg & 15;
        int grow = row0 + r;
        uint4 v = make_uint4(0u, 0u, 0u, 0u);
        if (grow < N_NODES) v = g_hh[(size_t)grow * 16 + u];
        sA[r * 16 + (u ^ (r & 7))] = v;
    }
    __syncthreads();

    unsigned sWb = (unsigned)__cvta_generic_to_shared(sW);
    unsigned sAb = (unsigned)__cvta_generic_to_shared(sA);

    float d[8][4];
    #pragma unroll
    for (int t = 0; t < 8; t++)
        #pragma unroll
        for (int c = 0; c < 4; c++) d[t][c] = 0.f;

    int lt = lane >> 3;
    int lj = lane & 7;

    #pragma unroll
    for (int k = 0; k < 8; k++) {
        unsigned a0, a1, a2, a3;
        {
            int rr = warp_m * 16 + ((lt & 1) << 3) + lj;
            int u  = (k << 1) + (lt >> 1);
            unsigned addr = sAb + ((rr << 4) + (u ^ (rr & 7))) * 16;
            asm volatile("ldmatrix.sync.aligned.m8n8.x4.shared.b16 {%0,%1,%2,%3}, [%4];"
                         : "=r"(a0), "=r"(a1), "=r"(a2), "=r"(a3) : "r"(addr));
        }
        #pragma unroll
        for (int p = 0; p < 4; p++) {
            int n0 = warp_n * 64 + p * 16;
            int rr = (k << 4) + ((lt & 1) << 3) + lj;
            int u  = (n0 >> 3) + (lt >> 1);
            unsigned addr = sWb + ((rr << 4) + (u ^ (rr & 7))) * 16;
            unsigned b00, b01, b10, b11;
            asm volatile("ldmatrix.sync.aligned.m8n8.x4.trans.shared.b16 {%0,%1,%2,%3}, [%4];"
                         : "=r"(b00), "=r"(b01), "=r"(b10), "=r"(b11) : "r"(addr));
            int t0 = 2 * p, t1 = 2 * p + 1;
            asm volatile("mma.sync.aligned.m16n8k16.row.col.f32.f16.f16.f32 "
                         "{%0,%1,%2,%3}, {%4,%5,%6,%7}, {%8,%9}, {%0,%1,%2,%3};"
                         : "+f"(d[t0][0]), "+f"(d[t0][1]), "+f"(d[t0][2]), "+f"(d[t0][3])
                         : "r"(a0), "r"(a1), "r"(a2), "r"(a3), "r"(b00), "r"(b01));
            asm volatile("mma.sync.aligned.m16n8k16.row.col.f32.f16.f16.f32 "
                         "{%0,%1,%2,%3}, {%4,%5,%6,%7}, {%8,%9}, {%0,%1,%2,%3};"
                         : "+f"(d[t1][0]), "+f"(d[t1][1]), "+f"(d[t1][2]), "+f"(d[t1][3])
                         : "r"(a0), "r"(a1), "r"(a2), "r"(a3), "r"(b10), "r"(b11));
        }
    }

    int r = lane >> 2;
    int c = (lane & 3) * 2;
    #pragma unroll
    for (int t = 0; t < 8; t++) {
        int col = warp_n * 64 + t * 8 + c;
        float2 bb = *reinterpret_cast<const float2*>(b + col);
        int grow = row0 + warp_m * 16 + r;
        if (grow < N_NODES) {
            float2 o;
            o.x = fmaxf(d[t][0] + bb.x, 0.f);
            o.y = fmaxf(d[t][1] + bb.y, 0.f);
            *reinterpret_cast<float2*>(out + (size_t)grow * D + col) = o;
        }
        int grow2 = grow + 8;
        if (grow2 < N_NODES) {
            float2 o;
            o.x = fmaxf(d[t][2] + bb.x, 0.f);
            o.y = fmaxf(d[t][3] + bb.y, 0.f);
            *reinterpret_cast<float2*>(out + (size_t)grow2 * D + col) = o;
        }
    }
}

// ---------------------------------------------------------------------------
// Inputs: feature f32[50000,128], edge_src i32[800000], edge_dst i32[800000],
// W f32[128,128], b f32[128]. Output f32[50000,128].
// ---------------------------------------------------------------------------
extern "C" void kernel_launch(void* const* d_in, const int* in_sizes, int n_in,
                              void* d_out, int out_size) {
    const float* feature  = (const float*)d_in[0];
    const int*   edge_src = (const int*)d_in[1];
    const int*   edge_dst = (const int*)d_in[2];
    const float* W        = (const float*)d_in[3];
    const float* b        = (const float*)d_in[4];
    float* out = (float*)d_out;

    hist_kernel<<<(N_EDGES / 4 + 255) / 256, 256>>>(edge_dst);
    scan1_kernel<<<N_BLKS, SCAN_B>>>();
    scan3_kernel<<<N_BLKS, SCAN_B>>>();
    bucket_kernel<<<(N_EDGES / 8 + 255) / 256, 256>>>(edge_src, edge_dst, feature, W);
    agg_kernel<<<(N_NODES * 32 + 255) / 256, 256>>>();
    gemm_kernel<<<(N_NODES + 63) / 64, 256>>>(b, out);
}

// round 16
// speedup vs baseline: 1.1032x; 1.1032x over previous
#include <cuda_runtime.h>
#include <cuda_fp16.h>
#include <cstdint>

#define N_NODES 50000
#define N_EDGES 800000
#define D 128
#define D4 (D / 4)
#define FULL 0xffffffffu
#define SCAN_B 1024
#define N_BLKS ((N_NODES + SCAN_B - 1) / SCAN_B)   // 49
#define N_TILES ((N_NODES + 63) / 64)              // 782
#define GEMM_GRID ((N_TILES + 1) / 2)              // 391 blocks x 2 tiles

// Static device scratch (no allocation; zero-initialized at load).
__device__ int   g_deg[N_NODES];
__device__ int   g_off[N_NODES + 1];
__device__ int   g_cursor[N_NODES];
__device__ int   g_csr[N_EDGES];
__device__ int   g_blk[64];                        // per-block scan sums
__device__ uint4 g_feat_h[(N_NODES + 1) * 16];     // fp16 rows; row N_NODES = zeros (never written)
__device__ uint4 g_hh[N_NODES * 16];               // fp16 aggregate h rows (256B)
__device__ uint2 g_Wh[D * D / 4];                  // fp16 W, row-major [k][n]

// ---------------------------------------------------------------------------
// K1: prep — feature f32->f16, W f32->f16, RED in-degree histogram (R12).
// g_deg cleared by the PREVIOUS execution's gemm kernel (zero at load).
// ---------------------------------------------------------------------------
__global__ void __launch_bounds__(256) prep_kernel(const float* __restrict__ feature,
                                                   const float* __restrict__ W,
                                                   const int* __restrict__ edge_dst) {
    int i = blockIdx.x * blockDim.x + threadIdx.x;
    if (i < N_NODES * D4) {
        float4 v = __ldg(reinterpret_cast<const float4*>(feature) + i);
        __half2 lo = __floats2half2_rn(v.x, v.y);
        __half2 hi = __floats2half2_rn(v.z, v.w);
        uint2 p;
        p.x = *reinterpret_cast<unsigned*>(&lo);
        p.y = *reinterpret_cast<unsigned*>(&hi);
        reinterpret_cast<uint2*>(g_feat_h)[i] = p;   // rows [0, N_NODES) only
    }
    if (i < D * D / 4) {
        float4 v = __ldg(reinterpret_cast<const float4*>(W) + i);
        __half2 lo = __floats2half2_rn(v.x, v.y);
        __half2 hi = __floats2half2_rn(v.z, v.w);
        uint2 p;
        p.x = *reinterpret_cast<unsigned*>(&lo);
        p.y = *reinterpret_cast<unsigned*>(&hi);
        g_Wh[i] = p;
    }
    if (i < N_EDGES / 4) {
        int4 d = __ldg(reinterpret_cast<const int4*>(edge_dst) + i);
        atomicAdd(&g_deg[d.x], 1);
        atomicAdd(&g_deg[d.y], 1);
        atomicAdd(&g_deg[d.z], 1);
        atomicAdd(&g_deg[d.w], 1);
    }
}

// ---------------------------------------------------------------------------
// K2: per-block exclusive scan (coalesced). Block total -> g_blk.
// ---------------------------------------------------------------------------
__global__ void __launch_bounds__(SCAN_B) scan1_kernel() {
    __shared__ int s_wsum[32];
    int t = threadIdx.x, wid = t >> 5, lane = t & 31;
    int i = blockIdx.x * SCAN_B + t;
    int v = (i < N_NODES) ? g_deg[i] : 0;

    int x = v;
    #pragma unroll
    for (int d = 1; d < 32; d <<= 1) {
        int y = __shfl_up_sync(FULL, x, d);
        if (lane >= d) x += y;
    }
    if (lane == 31) s_wsum[wid] = x;
    __syncthreads();
    if (wid == 0) {
        int w = s_wsum[lane];
        int xx = w;
        #pragma unroll
        for (int d = 1; d < 32; d <<= 1) {
            int y = __shfl_up_sync(FULL, xx, d);
            if (lane >= d) xx += y;
        }
        s_wsum[lane] = xx - w;
        if (lane == 31) g_blk[blockIdx.x] = xx;
    }
    __syncthreads();

    if (i < N_NODES) g_off[i] = (x - v) + s_wsum[wid];
}

// ---------------------------------------------------------------------------
// K3: add block offsets + init cursors; one warp re-scans the 49 totals.
// ---------------------------------------------------------------------------
__global__ void __launch_bounds__(SCAN_B) scan3_kernel() {
    __shared__ int s_off;
    int t = threadIdx.x;
    if (t < 32) {
        int v = 0;
        if (t < (int)blockIdx.x) v = g_blk[t];
        if (t + 32 < (int)blockIdx.x) v += g_blk[t + 32];
        #pragma unroll
        for (int d = 16; d >= 1; d >>= 1) v += __shfl_xor_sync(FULL, v, d);
        if (t == 0) s_off = v;
    }
    __syncthreads();

    int i = blockIdx.x * SCAN_B + t;
    if (i < N_NODES) {
        int off = g_off[i] + s_off;
        g_off[i] = off;
        g_cursor[i] = off;
    }
    if (i == 0) g_off[N_NODES] = N_EDGES;
}

// ---------------------------------------------------------------------------
// K4: bucket fill (atomic MLP-4, R12-proven).
// ---------------------------------------------------------------------------
__global__ void bucket_kernel(const int* __restrict__ edge_src,
                              const int* __restrict__ edge_dst) {
    int i = blockIdx.x * blockDim.x + threadIdx.x;
    if (i < N_EDGES / 4) {
        int4 d = reinterpret_cast<const int4*>(edge_dst)[i];
        int4 s = reinterpret_cast<const int4*>(edge_src)[i];
        g_csr[atomicAdd(&g_cursor[d.x], 1)] = s.x;
        g_csr[atomicAdd(&g_cursor[d.y], 1)] = s.y;
        g_csr[atomicAdd(&g_cursor[d.z], 1)] = s.z;
        g_csr[atomicAdd(&g_cursor[d.w], 1)] = s.w;
    }
}

// ---------------------------------------------------------------------------
// K5: aggregate — one warp per node, half-warp per fp16 row, uniform padded
// 8-edge body with TWO HADD2 tree levels (numerics validated in R14).
// ---------------------------------------------------------------------------
__device__ __forceinline__ void acc8(float* acc, uint4 a) {
    float2 f0 = __half22float2(*reinterpret_cast<__half2*>(&a.x));
    float2 f1 = __half22float2(*reinterpret_cast<__half2*>(&a.y));
    float2 f2 = __half22float2(*reinterpret_cast<__half2*>(&a.z));
    float2 f3 = __half22float2(*reinterpret_cast<__half2*>(&a.w));
    acc[0] += f0.x; acc[1] += f0.y; acc[2] += f1.x; acc[3] += f1.y;
    acc[4] += f2.x; acc[5] += f2.y; acc[6] += f3.x; acc[7] += f3.y;
}

__device__ __forceinline__ uint4 hadd2_u4(uint4 a, uint4 b) {
    uint4 r;
    __half2 x, y;
    x = *reinterpret_cast<__half2*>(&a.x); y = *reinterpret_cast<__half2*>(&b.x);
    x = __hadd2(x, y); r.x = *reinterpret_cast<unsigned*>(&x);
    x = *reinterpret_cast<__half2*>(&a.y); y = *reinterpret_cast<__half2*>(&b.y);
    x = __hadd2(x, y); r.y = *reinterpret_cast<unsigned*>(&x);
    x = *reinterpret_cast<__half2*>(&a.z); y = *reinterpret_cast<__half2*>(&b.z);
    x = __hadd2(x, y); r.z = *reinterpret_cast<unsigned*>(&x);
    x = *reinterpret_cast<__half2*>(&a.w); y = *reinterpret_cast<__half2*>(&b.w);
    x = __hadd2(x, y); r.w = *reinterpret_cast<unsigned*>(&x);
    return r;
}

__global__ void __launch_bounds__(256) agg_kernel() {
    int w = (blockIdx.x * blockDim.x + threadIdx.x) >> 5;
    int lane = threadIdx.x & 31;
    if (w >= N_NODES) return;
    int half = lane >> 4;
    int hl   = lane & 15;

    int j0 = g_off[w];
    int len = g_off[w + 1] - j0;

    const uint4* fh = g_feat_h;
    float acc[8];
    #pragma unroll
    for (int i = 0; i < 8; i++) acc[i] = 0.f;

    for (int base = 0; base < len; base += 32) {
        int rem = len - base;
        int nb = rem < 32 ? rem : 32;
        int myidx = N_NODES;                       // default: zero row
        if (base + lane < len) myidx = g_csr[j0 + base + lane];

        for (int t = 0; t < nb; t += 8) {          // always full 8-edge body
            int s0 = __shfl_sync(FULL, myidx, t + 0 + half);
            int s1 = __shfl_sync(FULL, myidx, t + 2 + half);
            int s2 = __shfl_sync(FULL, myidx, t + 4 + half);
            int s3 = __shfl_sync(FULL, myidx, t + 6 + half);
            uint4 a0 = __ldg(fh + (size_t)s0 * 16 + hl);
            uint4 a1 = __ldg(fh + (size_t)s1 * 16 + hl);
            uint4 a2 = __ldg(fh + (size_t)s2 * 16 + hl);
            uint4 a3 = __ldg(fh + (size_t)s3 * 16 + hl);
            uint4 p01 = hadd2_u4(a0, a1);
            uint4 p23 = hadd2_u4(a2, a3);
            uint4 q   = hadd2_u4(p01, p23);        // second tree level
            acc8(acc, q);
        }
    }

    #pragma unroll
    for (int i = 0; i < 8; i++)
        acc[i] += __shfl_xor_sync(FULL, acc[i], 16);

    if (half == 0) {
        __half2 h0 = __floats2half2_rn(acc[0], acc[1]);
        __half2 h1 = __floats2half2_rn(acc[2], acc[3]);
        __half2 h2 = __floats2half2_rn(acc[4], acc[5]);
        __half2 h3 = __floats2half2_rn(acc[6], acc[7]);
        uint4 p;
        p.x = *reinterpret_cast<unsigned*>(&h0);
        p.y = *reinterpret_cast<unsigned*>(&h1);
        p.z = *reinterpret_cast<unsigned*>(&h2);
        p.w = *reinterpret_cast<unsigned*>(&h3);
        g_hh[(size_t)w * 16 + hl] = p;
    }
}

// ---------------------------------------------------------------------------
// K6: PERSISTENT tensor-core GEMM — 391 blocks, exactly 2 tiles each; W is
// staged to smem ONCE per block (halves W L2 traffic). Clears g_deg for the
// NEXT execution.
// ---------------------------------------------------------------------------
__global__ void __launch_bounds__(256) gemm_kernel(const float* __restrict__ b,
                                                   float* __restrict__ out) {
    __shared__ uint4 sW[D * 16];    // 32 KB
    __shared__ uint4 sA[64 * 16];   // 16 KB

    int tid = threadIdx.x;
    int warp = tid >> 5;
    int lane = tid & 31;
    int warp_m = warp >> 1;
    int warp_n = warp & 1;
    int lt = lane >> 3;
    int lj = lane & 7;

    {   // clear g_deg for next execution (391*256 = 100096 >= 50000)
        int gid = blockIdx.x * 256 + tid;
        if (gid < N_NODES) g_deg[gid] = 0;
    }

    // Stage W once per block.
    #pragma unroll
    for (int it = 0; it < 8; it++) {
        int seg = tid + it * 256;
        int row = seg >> 4, u = seg & 15;
        sW[row * 16 + (u ^ (row & 7))] = reinterpret_cast<const uint4*>(g_Wh)[seg];
    }

    unsigned sWb = (unsigned)__cvta_generic_to_shared(sW);
    unsigned sAb = (unsigned)__cvta_generic_to_shared(sA);

    #pragma unroll
    for (int rep = 0; rep < 2; rep++) {
        int tile = blockIdx.x * 2 + rep;
        int row0 = tile * 64;
        __syncthreads();   // W staged (first iter) / prev tile's mma done (second)

        #pragma unroll
        for (int it = 0; it < 4; it++) {
            int seg = tid + it * 256;
            int r = seg >> 4, u = seg & 15;
            int grow = row0 + r;
            uint4 v = make_uint4(0u, 0u, 0u, 0u);
            if (grow < N_NODES) v = g_hh[(size_t)grow * 16 + u];
            sA[r * 16 + (u ^ (r & 7))] = v;
        }
        __syncthreads();

        float d[8][4];
        #pragma unroll
        for (int t = 0; t < 8; t++)
            #pragma unroll
            for (int c = 0; c < 4; c++) d[t][c] = 0.f;

        #pragma unroll
        for (int k = 0; k < 8; k++) {
            unsigned a0, a1, a2, a3;
            {
                int rr = warp_m * 16 + ((lt & 1) << 3) + lj;
                int u  = (k << 1) + (lt >> 1);
                unsigned addr = sAb + ((rr << 4) + (u ^ (rr & 7))) * 16;
                asm volatile("ldmatrix.sync.aligned.m8n8.x4.shared.b16 {%0,%1,%2,%3}, [%4];"
                             : "=r"(a0), "=r"(a1), "=r"(a2), "=r"(a3) : "r"(addr));
            }
            #pragma unroll
            for (int p = 0; p < 4; p++) {
                int n0 = warp_n * 64 + p * 16;
                int rr = (k << 4) + ((lt & 1) << 3) + lj;
                int u  = (n0 >> 3) + (lt >> 1);
                unsigned addr = sWb + ((rr << 4) + (u ^ (rr & 7))) * 16;
                unsigned b00, b01, b10, b11;
                asm volatile("ldmatrix.sync.aligned.m8n8.x4.trans.shared.b16 {%0,%1,%2,%3}, [%4];"
                             : "=r"(b00), "=r"(b01), "=r"(b10), "=r"(b11) : "r"(addr));
                int t0 = 2 * p, t1 = 2 * p + 1;
                asm volatile("mma.sync.aligned.m16n8k16.row.col.f32.f16.f16.f32 "
                             "{%0,%1,%2,%3}, {%4,%5,%6,%7}, {%8,%9}, {%0,%1,%2,%3};"
                             : "+f"(d[t0][0]), "+f"(d[t0][1]), "+f"(d[t0][2]), "+f"(d[t0][3])
                             : "r"(a0), "r"(a1), "r"(a2), "r"(a3), "r"(b00), "r"(b01));
                asm volatile("mma.sync.aligned.m16n8k16.row.col.f32.f16.f16.f32 "
                             "{%0,%1,%2,%3}, {%4,%5,%6,%7}, {%8,%9}, {%0,%1,%2,%3};"
                             : "+f"(d[t1][0]), "+f"(d[t1][1]), "+f"(d[t1][2]), "+f"(d[t1][3])
                             : "r"(a0), "r"(a1), "r"(a2), "r"(a3), "r"(b10), "r"(b11));
            }
        }

        int r = lane >> 2;
        int c = (lane & 3) * 2;
        #pragma unroll
        for (int t = 0; t < 8; t++) {
            int col = warp_n * 64 + t * 8 + c;
            float2 bb = *reinterpret_cast<const float2*>(b + col);
            int grow = row0 + warp_m * 16 + r;
            if (grow < N_NODES) {
                float2 o;
                o.x = fmaxf(d[t][0] + bb.x, 0.f);
                o.y = fmaxf(d[t][1] + bb.y, 0.f);
                *reinterpret_cast<float2*>(out + (size_t)grow * D + col) = o;
            }
            int grow2 = grow + 8;
            if (grow2 < N_NODES) {
                float2 o;
                o.x = fmaxf(d[t][2] + bb.x, 0.f);
                o.y = fmaxf(d[t][3] + bb.y, 0.f);
                *reinterpret_cast<float2*>(out + (size_t)grow2 * D + col) = o;
            }
        }
    }
}

// ---------------------------------------------------------------------------
// Inputs: feature f32[50000,128], edge_src i32[800000], edge_dst i32[800000],
// W f32[128,128], b f32[128]. Output f32[50000,128].
// ---------------------------------------------------------------------------
extern "C" void kernel_launch(void* const* d_in, const int* in_sizes, int n_in,
                              void* d_out, int out_size) {
    const float* feature  = (const float*)d_in[0];
    const int*   edge_src = (const int*)d_in[1];
    const int*   edge_dst = (const int*)d_in[2];
    const float* W        = (const float*)d_in[3];
    const float* b        = (const float*)d_in[4];
    float* out = (float*)d_out;

    prep_kernel<<<(N_NODES * D4 + 255) / 256, 256>>>(feature, W, edge_dst);
    scan1_kernel<<<N_BLKS, SCAN_B>>>();
    scan3_kernel<<<N_BLKS, SCAN_B>>>();
    bucket_kernel<<<(N_EDGES / 4 + 255) / 256, 256>>>(edge_src, edge_dst);
    agg_kernel<<<(N_NODES * 32 + 255) / 256, 256>>>();
    gemm_kernel<<<GEMM_GRID, 256>>>(b, out);
}